// round 1
// baseline (speedup 1.0000x reference)
#include <cuda_runtime.h>
#include <cuda_bf16.h>
#include <cstdint>
#include <math.h>

// Problem constants
#define NN      20000
#define DEG     16
#define CIN     128
#define COUT    128
#define TT      3
#define HID     128
#define EPS_SEL 0.01f
// Derived
#define SG_M    640      // 256 (4 slots x 64 scoring) + 384 (GRU input proj)
#define GH_M    384

// ---------------- device scratch (static, no allocation) ----------------
__device__ float g_SG   [(size_t)NN * SG_M];   // [N,640]: cols 0..255 = slot contribs (b1 folded into slot0), 256..639 = G = v@Wih^T + bih
__device__ float g_GH   [(size_t)NN * GH_M];   // gh scratch per GRU step
__device__ float g_base [(size_t)NN * 64];     // running scoring base (incl b1)
__device__ float g_h    [(size_t)NN * HID];    // GRU hidden state
__device__ int   g_walks[NN];
__device__ int   g_sel  [TT * NN];
__device__ float g_B1   [128 * SG_M];          // combined weight for big precompute GEMM
__device__ float g_bias1[SG_M];
__device__ float g_WhhT [128 * GH_M];          // Whh^T, [k][j]

// ---------------- weight prep ----------------
__global__ void prep_weights(const float* __restrict__ W1, const float* __restrict__ b1,
                             const float* __restrict__ Wih, const float* __restrict__ bih,
                             const float* __restrict__ Whh) {
    int i = blockIdx.x * blockDim.x + threadIdx.x;
    const int total1 = 128 * SG_M;
    if (i < total1) {
        int k = i / SG_M, j = i % SG_M;
        float val;
        if (j < 256) {                       // scoring slot s, output m
            int s = j >> 6, m = j & 63;
            val = W1[(size_t)(s * 128 + k) * 64 + m];
        } else {                             // Wih^T
            int c = j - 256;
            val = Wih[(size_t)c * 128 + k];
        }
        g_B1[i] = val;
        if (k == 0)
            g_bias1[j] = (j < 64) ? b1[j] : ((j < 256) ? 0.0f : bih[j - 256]);
    } else {
        int i2 = i - total1;
        if (i2 < 128 * GH_M) {
            int k = i2 / GH_M, j = i2 % GH_M;
            g_WhhT[i2] = Whh[(size_t)j * 128 + k];
        }
    }
}

// ---------------- generic fp32 GEMM: C[rows,M] = A[rows,128] * B[128,M] + bias[M] ----------------
// BM=64 BN=64 BK=16, 256 threads, 4x4 per thread.
__global__ void sgemm128(const float* __restrict__ A, const float* __restrict__ B,
                         const float* __restrict__ bias, float* __restrict__ C,
                         int rows, int M) {
    __shared__ float As[16][64];
    __shared__ float Bs[16][64];
    int tid = threadIdx.x;
    int tx = tid & 15, ty = tid >> 4;
    int rowBase = blockIdx.y * 64;
    int colBase = blockIdx.x * 64;

    float acc[4][4];
#pragma unroll
    for (int i = 0; i < 4; i++)
#pragma unroll
        for (int j = 0; j < 4; j++) acc[i][j] = 0.0f;

    for (int k0 = 0; k0 < 128; k0 += 16) {
        // A tile: 64 rows x 16 k
        {
            int r = tid >> 2;
            int kv = (tid & 3) * 4;
            int grow = rowBase + r;
            float4 a4 = make_float4(0.f, 0.f, 0.f, 0.f);
            if (grow < rows)
                a4 = *(const float4*)(A + (size_t)grow * 128 + k0 + kv);
            As[kv + 0][r] = a4.x;
            As[kv + 1][r] = a4.y;
            As[kv + 2][r] = a4.z;
            As[kv + 3][r] = a4.w;
        }
        // B tile: 16 k x 64 cols
        {
            int kk = tid >> 4;
            int cc = (tid & 15) * 4;
            float4 b4 = *(const float4*)(B + (size_t)(k0 + kk) * M + colBase + cc);
            *(float4*)&Bs[kk][cc] = b4;
        }
        __syncthreads();
#pragma unroll
        for (int k = 0; k < 16; k++) {
            float a[4], b[4];
#pragma unroll
            for (int i = 0; i < 4; i++) a[i] = As[k][ty * 4 + i];
#pragma unroll
            for (int j = 0; j < 4; j++) b[j] = Bs[k][tx * 4 + j];
#pragma unroll
            for (int i = 0; i < 4; i++)
#pragma unroll
                for (int j = 0; j < 4; j++) acc[i][j] = fmaf(a[i], b[j], acc[i][j]);
        }
        __syncthreads();
    }
#pragma unroll
    for (int i = 0; i < 4; i++) {
        int grow = rowBase + ty * 4 + i;
        if (grow >= rows) break;
#pragma unroll
        for (int j = 0; j < 4; j++) {
            int gc = colBase + tx * 4 + j;
            C[(size_t)grow * M + gc] = acc[i][j] + bias[gc];
        }
    }
}

// ---------------- init: walks=n, base = slot0 contrib (b1 already folded in) ----------------
__global__ void init_walk() {
    int i = blockIdx.x * blockDim.x + threadIdx.x;
    if (i >= NN * 64) return;
    int n = i >> 6, m = i & 63;
    g_base[i] = g_SG[(size_t)n * SG_M + m];
    if (m == 0) g_walks[n] = n;
}

// ---------------- walk step: one warp per node ----------------
__global__ void walk_step(const int* __restrict__ dst, const float* __restrict__ W2,
                          const float* __restrict__ b2p, const float* __restrict__ noise,
                          int t) {
    const unsigned FULL = 0xFFFFFFFFu;
    int gwarp = (blockIdx.x * blockDim.x + threadIdx.x) >> 5;
    int lane = threadIdx.x & 31;
    int wz = threadIdx.x >> 5;
    __shared__ float s_logp[8][16];
    if (gwarp >= NN) return;
    int n = gwarp;
    int cur = g_walks[n];

    const float2* baserow = (const float2*)(g_base + (size_t)n * 64);
    float2 bse = baserow[lane];
    float2 w2  = ((const float2*)W2)[lane];
    float  b2  = b2p[0];
    const int* nb = dst + (size_t)cur * DEG;
    const int slot_off = (1 + t) * 64;

#pragma unroll
    for (int d = 0; d < DEG; d++) {
        int cand = nb[d];
        const float2* crow = (const float2*)(g_SG + (size_t)cand * SG_M + slot_off);
        float2 c = crow[lane];
        float s = fmaxf(bse.x + c.x, 0.f) * w2.x + fmaxf(bse.y + c.y, 0.f) * w2.y;
#pragma unroll
        for (int off = 16; off >= 1; off >>= 1)
            s += __shfl_xor_sync(FULL, s, off);
        if (lane == 0) s_logp[wz][d] = s + b2;
    }
    __syncwarp();

    float lp = (lane < DEG) ? s_logp[wz][lane] : -1e38f;
    float m = lp;
#pragma unroll
    for (int off = 16; off >= 1; off >>= 1)
        m = fmaxf(m, __shfl_xor_sync(FULL, m, off));
    float e = (lane < DEG) ? expf(lp - m) : 0.0f;
    float ssum = e;
#pragma unroll
    for (int off = 16; off >= 1; off >>= 1)
        ssum += __shfl_xor_sync(FULL, ssum, off);
    float norm = m + logf(ssum);
    float p = (lane < DEG)
                  ? expf(lp - norm) + EPS_SEL * noise[((size_t)t * NN + n) * DEG + lane]
                  : -1e38f;
    // argmax (first-index on ties, matching jnp.argmax)
    float bv = p;
    int bi = lane;
#pragma unroll
    for (int off = 16; off >= 1; off >>= 1) {
        float ov = __shfl_xor_sync(FULL, bv, off);
        int oi = __shfl_xor_sync(FULL, bi, off);
        if (ov > bv || (ov == bv && oi < bi)) { bv = ov; bi = oi; }
    }
    int csel = nb[bi];
    const float2* crow = (const float2*)(g_SG + (size_t)csel * SG_M + slot_off);
    float2 c = crow[lane];
    bse.x += c.x;
    bse.y += c.y;
    ((float2*)(g_base + (size_t)n * 64))[lane] = bse;
    if (lane == 0) {
        g_walks[n] = csel;
        g_sel[t * NN + n] = csel;
    }
}

// ---------------- GRU elementwise gates ----------------
__global__ void gru_elem(const float* __restrict__ bhh, int s) {
    int i = blockIdx.x * blockDim.x + threadIdx.x;
    if (i >= NN * HID) return;
    int n = i >> 7, c = i & 127;
    int src = (s == 0) ? n : g_sel[(s - 1) * NN + n];
    const float* gi = g_SG + (size_t)src * SG_M + 256;
    float gir = gi[c], giz = gi[128 + c], gin = gi[256 + c];
    float ghr, ghz, ghn, hprev;
    if (s == 0) {
        ghr = bhh[c]; ghz = bhh[128 + c]; ghn = bhh[256 + c];
        hprev = 0.0f;
    } else {
        const float* gh = g_GH + (size_t)n * GH_M;
        ghr = gh[c]; ghz = gh[128 + c]; ghn = gh[256 + c];
        hprev = g_h[i];
    }
    float r = 1.0f / (1.0f + expf(-(gir + ghr)));
    float z = 1.0f / (1.0f + expf(-(giz + ghz)));
    float nn2 = tanhf(gin + r * ghn);
    g_h[i] = (1.0f - z) * nn2 + z * hprev;
}

// ---------------- host launch ----------------
extern "C" void kernel_launch(void* const* d_in, const int* in_sizes, int n_in,
                              void* d_out, int out_size) {
    const float* node_attr = (const float*)d_in[0];
    const int*   edge_idx  = (const int*)d_in[1];
    // d_in[2] slices unused
    const float* W1   = (const float*)d_in[3];
    const float* b1   = (const float*)d_in[4];
    const float* W2   = (const float*)d_in[5];
    const float* b2   = (const float*)d_in[6];
    const float* Wih  = (const float*)d_in[7];
    const float* Whh  = (const float*)d_in[8];
    const float* bih  = (const float*)d_in[9];
    const float* bhh  = (const float*)d_in[10];
    const float* Wout = (const float*)d_in[11];
    const float* bout = (const float*)d_in[12];
    const float* noise = (const float*)d_in[13];
    float* out = (float*)d_out;
    const int* dst = edge_idx + (size_t)NN * DEG;  // edge_index[1]

    float *pSG, *pGH, *pH, *pB1, *pBias1, *pWhhT;
    cudaGetSymbolAddress((void**)&pSG, g_SG);
    cudaGetSymbolAddress((void**)&pGH, g_GH);
    cudaGetSymbolAddress((void**)&pH, g_h);
    cudaGetSymbolAddress((void**)&pB1, g_B1);
    cudaGetSymbolAddress((void**)&pBias1, g_bias1);
    cudaGetSymbolAddress((void**)&pWhhT, g_WhhT);

    // 1. weight prep
    {
        int total = 128 * SG_M + 128 * GH_M;
        prep_weights<<<(total + 255) / 256, 256>>>(W1, b1, Wih, bih, Whh);
    }
    // 2. big precompute GEMM: SG = v @ [W1' | Wih^T] + [b1-in-slot0 | 0 | bih]
    {
        dim3 grid(SG_M / 64, (NN + 63) / 64);
        sgemm128<<<grid, 256>>>(node_attr, pB1, pBias1, pSG, NN, SG_M);
    }
    // 3. init walk state
    init_walk<<<(NN * 64 + 255) / 256, 256>>>();
    // 4. three walk-selection steps
    for (int t = 0; t < TT; t++)
        walk_step<<<(NN * 32 + 255) / 256, 256>>>(dst, W2, b2, noise, t);
    // 5. GRU over 4 timesteps (step 0: h_prev = 0 so gh = bhh, no GEMM)
    gru_elem<<<(NN * HID + 255) / 256, 256>>>(bhh, 0);
    for (int s = 1; s <= TT; s++) {
        dim3 grid(GH_M / 64, (NN + 63) / 64);
        sgemm128<<<grid, 256>>>(pH, pWhhT, bhh, pGH, NN, GH_M);
        gru_elem<<<(NN * HID + 255) / 256, 256>>>(bhh, s);
    }
    // 6. output projection: out = h @ Wout + bout  (Wout is [128,128] row-major = B directly)
    {
        dim3 grid(COUT / 64, (NN + 63) / 64);
        sgemm128<<<grid, 256>>>(pH, Wout, bout, out, NN, COUT);
    }
}

// round 3
// speedup vs baseline: 1.0908x; 1.0908x over previous
#include <cuda_runtime.h>
#include <cuda_fp16.h>
#include <cstdint>
#include <math.h>

// Problem constants
#define NN      20000
#define DEG     16
#define TT      3
#define HID     128
#define EPS_SEL 0.01f
#define SC_M    256      // 4 slots x 64 scoring cols (fp32 path)
#define GH_M    384

// ---------------- device scratch ----------------
__device__ float g_SC   [(size_t)NN * SC_M];   // scoring slot contribs (b1 folded into slot0)
__device__ float g_G    [(size_t)NN * GH_M];   // v @ Wih^T + bih
__device__ float g_GH   [(size_t)NN * GH_M];   // gh per GRU step
__device__ float g_base [(size_t)NN * 64];
__device__ float g_h    [(size_t)NN * HID];
__device__ int   g_walks[NN];
__device__ int   g_sel  [TT * NN];
__device__ float g_Bsc  [128 * SC_M];          // scoring weights [k][j]
__device__ float g_bias_sc[SC_M];
__device__ __half g_Wih_h[GH_M * 128], g_Wih_l[GH_M * 128];   // [n][k]
__device__ __half g_Whh_h[GH_M * 128], g_Whh_l[GH_M * 128];   // [n][k]
__device__ __half g_Wout_h[128 * 128], g_Wout_l[128 * 128];   // [n][k] (transposed)

__device__ __forceinline__ uint32_t smem_u32(const void* p) {
    uint32_t a;
    asm("{ .reg .u64 t; cvta.to.shared.u64 t, %1; cvt.u32.u64 %0, t; }" : "=r"(a) : "l"(p));
    return a;
}

// ---------------- weight prep ----------------
__global__ void prep_weights(const float* __restrict__ W1, const float* __restrict__ b1,
                             const float* __restrict__ Wih, const float* __restrict__ Whh,
                             const float* __restrict__ Wout) {
    int i = blockIdx.x * blockDim.x + threadIdx.x;
    if (i < 128 * SC_M) {
        int k = i / SC_M, j = i % SC_M;
        int s = j >> 6, m = j & 63;
        g_Bsc[i] = W1[(size_t)(s * 128 + k) * 64 + m];
        if (k == 0) g_bias_sc[j] = (j < 64) ? b1[j] : 0.0f;
        return;
    }
    int i2 = i - 128 * SC_M;
    float w;
    __half *dh, *dl;
    if (i2 < GH_M * 128) { w = Wih[i2]; dh = g_Wih_h; dl = g_Wih_l; }
    else if (i2 < 2 * GH_M * 128) { i2 -= GH_M * 128; w = Whh[i2]; dh = g_Whh_h; dl = g_Whh_l; }
    else {
        i2 -= 2 * GH_M * 128;
        if (i2 >= 128 * 128) return;
        int n = i2 / 128, k = i2 % 128;
        w = Wout[(size_t)k * 128 + n];
        dh = g_Wout_h; dl = g_Wout_l;
    }
    __half hi = __float2half_rn(w);
    dh[i2] = hi;
    dl[i2] = __float2half_rn(w - __half2float(hi));
}

// ---------------- mma.sync fp16x2-split GEMM ----------------
// C[row, bx*128 + j] = sum_k A[row,k] * W[bx*128+j, k] + bias[bx*128+j]
// A fp32 [rows,128]; W pre-split hi/lo fp16 [N][128]. 3-term split: hh + hl + lh.
#define LDS 136   // padded half stride
__global__ __launch_bounds__(256, 1) void mma_gemm(const float* __restrict__ A,
                                                   const __half* __restrict__ Bh,
                                                   const __half* __restrict__ Bl,
                                                   const float* __restrict__ bias,
                                                   float* __restrict__ C, int rows, int ldc) {
    extern __shared__ __align__(16) char smem[];
    const int AH_OFF = 0;
    const int AL_OFF = 128 * LDS * 2;
    const int BH_OFF = 2 * 128 * LDS * 2;
    const int BL_OFF = 3 * 128 * LDS * 2;
    uint32_t sb = smem_u32(smem);

    int tid = threadIdx.x;
    int lane = tid & 31;
    int wid = tid >> 5;
    int wm = wid >> 1, wn = wid & 1;
    int rowBase = blockIdx.y * 128;

    // ---- load A (fp32 -> hi/lo fp16, padded) ----
    for (int c = tid; c < 4096; c += 256) {
        int r = c >> 5, k = (c & 31) * 4;
        int gr = rowBase + r;
        float4 a = make_float4(0.f, 0.f, 0.f, 0.f);
        if (gr < rows) a = *(const float4*)(A + (size_t)gr * 128 + k);
        float av[4] = {a.x, a.y, a.z, a.w};
        __half hv[4], lv[4];
#pragma unroll
        for (int q = 0; q < 4; q++) {
            hv[q] = __float2half_rn(av[q]);
            lv[q] = __float2half_rn(av[q] - __half2float(hv[q]));
        }
        size_t off = ((size_t)r * LDS + k) * 2;
        *(uint2*)(smem + AH_OFF + off) = *(uint2*)hv;
        *(uint2*)(smem + AL_OFF + off) = *(uint2*)lv;
    }
    // ---- load B tiles (pre-split halves) ----
    {
        const __half* bh = Bh + (size_t)blockIdx.x * 128 * 128;
        const __half* bl = Bl + (size_t)blockIdx.x * 128 * 128;
        for (int c = tid; c < 4096; c += 256) {
            int r = c >> 5, k = (c & 31) * 4;
            size_t off = ((size_t)r * LDS + k) * 2;
            *(uint2*)(smem + BH_OFF + off) = *(const uint2*)(bh + r * 128 + k);
            *(uint2*)(smem + BL_OFF + off) = *(const uint2*)(bl + r * 128 + k);
        }
    }
    __syncthreads();

    float acc[2][8][4];
#pragma unroll
    for (int mi = 0; mi < 2; mi++)
#pragma unroll
        for (int ni = 0; ni < 8; ni++)
#pragma unroll
            for (int q = 0; q < 4; q++) acc[mi][ni][q] = 0.0f;

    const int aOffT[3] = {AH_OFF, AH_OFF, AL_OFF};
    const int bOffT[3] = {BH_OFF, BL_OFF, BH_OFF};
    int a_r = lane & 15;
    int a_c = (lane >> 4) * 8;
    int b_r = (lane & 7) + ((lane >> 4) << 3);
    int b_c = ((lane >> 3) & 1) * 8;

#pragma unroll
    for (int term = 0; term < 3; term++) {
        uint32_t abase = sb + aOffT[term];
        uint32_t bbase = sb + bOffT[term];
#pragma unroll
        for (int k0 = 0; k0 < 8; k0++) {
            int kk = k0 * 16;
            uint32_t af[2][4];
#pragma unroll
            for (int mi = 0; mi < 2; mi++) {
                uint32_t addr = abase + (uint32_t)(((wm * 32 + mi * 16 + a_r) * LDS + kk + a_c) * 2);
                asm volatile("ldmatrix.sync.aligned.m8n8.x4.shared.b16 {%0,%1,%2,%3}, [%4];"
                             : "=r"(af[mi][0]), "=r"(af[mi][1]), "=r"(af[mi][2]), "=r"(af[mi][3])
                             : "r"(addr));
            }
            uint32_t bf[8][2];
#pragma unroll
            for (int nj = 0; nj < 4; nj++) {
                uint32_t addr = bbase + (uint32_t)(((wn * 64 + nj * 16 + b_r) * LDS + kk + b_c) * 2);
                uint32_t r0, r1, r2, r3;
                asm volatile("ldmatrix.sync.aligned.m8n8.x4.shared.b16 {%0,%1,%2,%3}, [%4];"
                             : "=r"(r0), "=r"(r1), "=r"(r2), "=r"(r3)
                             : "r"(addr));
                bf[2 * nj][0] = r0; bf[2 * nj][1] = r1;
                bf[2 * nj + 1][0] = r2; bf[2 * nj + 1][1] = r3;
            }
#pragma unroll
            for (int mi = 0; mi < 2; mi++)
#pragma unroll
                for (int ni = 0; ni < 8; ni++) {
                    asm volatile(
                        "mma.sync.aligned.m16n8k16.row.col.f32.f16.f16.f32 "
                        "{%0,%1,%2,%3}, {%4,%5,%6,%7}, {%8,%9}, {%0,%1,%2,%3};"
                        : "+f"(acc[mi][ni][0]), "+f"(acc[mi][ni][1]),
                          "+f"(acc[mi][ni][2]), "+f"(acc[mi][ni][3])
                        : "r"(af[mi][0]), "r"(af[mi][1]), "r"(af[mi][2]), "r"(af[mi][3]),
                          "r"(bf[ni][0]), "r"(bf[ni][1]));
                }
        }
    }

    // ---- epilogue ----
    int rb = rowBase + wm * 32;
    int cb = blockIdx.x * 128 + wn * 64;
#pragma unroll
    for (int mi = 0; mi < 2; mi++) {
#pragma unroll
        for (int ni = 0; ni < 8; ni++) {
            int r0 = rb + mi * 16 + (lane >> 2);
            int c0 = cb + ni * 8 + (lane & 3) * 2;
            float bv0 = bias[c0], bv1 = bias[c0 + 1];
            if (r0 < rows) {
                float2 o = make_float2(acc[mi][ni][0] + bv0, acc[mi][ni][1] + bv1);
                *(float2*)(C + (size_t)r0 * ldc + c0) = o;
            }
            if (r0 + 8 < rows) {
                float2 o = make_float2(acc[mi][ni][2] + bv0, acc[mi][ni][3] + bv1);
                *(float2*)(C + (size_t)(r0 + 8) * ldc + c0) = o;
            }
        }
    }
}
#define MMA_SMEM (4 * 128 * LDS * 2)

// ---------------- fp32 scoring GEMM: C = A[rows,128] @ B[128,256] + bias ----------------
__global__ void sgemm_score(const float* __restrict__ A, float* __restrict__ C, int rows) {
    __shared__ float As[16][64];
    __shared__ float Bs[16][64];
    int tid = threadIdx.x;
    int tx = tid & 15, ty = tid >> 4;
    int rowBase = blockIdx.y * 64;
    int colBase = blockIdx.x * 64;

    float acc[4][4];
#pragma unroll
    for (int i = 0; i < 4; i++)
#pragma unroll
        for (int j = 0; j < 4; j++) acc[i][j] = 0.0f;

    for (int k0 = 0; k0 < 128; k0 += 16) {
        {
            int r = tid >> 2;
            int kv = (tid & 3) * 4;
            int grow = rowBase + r;
            float4 a4 = make_float4(0.f, 0.f, 0.f, 0.f);
            if (grow < rows) a4 = *(const float4*)(A + (size_t)grow * 128 + k0 + kv);
            As[kv + 0][r] = a4.x; As[kv + 1][r] = a4.y;
            As[kv + 2][r] = a4.z; As[kv + 3][r] = a4.w;
        }
        {
            int kk = tid >> 4;
            int cc = (tid & 15) * 4;
            float4 b4 = *(const float4*)(g_Bsc + (size_t)(k0 + kk) * SC_M + colBase + cc);
            *(float4*)&Bs[kk][cc] = b4;
        }
        __syncthreads();
#pragma unroll
        for (int k = 0; k < 16; k++) {
            float a[4], b[4];
#pragma unroll
            for (int i = 0; i < 4; i++) a[i] = As[k][ty * 4 + i];
#pragma unroll
            for (int j = 0; j < 4; j++) b[j] = Bs[k][tx * 4 + j];
#pragma unroll
            for (int i = 0; i < 4; i++)
#pragma unroll
                for (int j = 0; j < 4; j++) acc[i][j] = fmaf(a[i], b[j], acc[i][j]);
        }
        __syncthreads();
    }
#pragma unroll
    for (int i = 0; i < 4; i++) {
        int grow = rowBase + ty * 4 + i;
        if (grow >= rows) break;
#pragma unroll
        for (int j = 0; j < 4; j++) {
            int gc = colBase + tx * 4 + j;
            float v = acc[i][j] + g_bias_sc[gc];
            C[(size_t)grow * SC_M + gc] = v;
            if (gc < 64) g_base[(size_t)grow * 64 + gc] = v;  // slot0 + b1 = initial base
        }
    }
}

// ---------------- walk step: one warp per node ----------------
__global__ void walk_step(const int* __restrict__ dst, const float* __restrict__ W2,
                          const float* __restrict__ b2p, const float* __restrict__ noise,
                          int t) {
    const unsigned FULL = 0xFFFFFFFFu;
    int gwarp = (blockIdx.x * blockDim.x + threadIdx.x) >> 5;
    int lane = threadIdx.x & 31;
    int wz = threadIdx.x >> 5;
    __shared__ float s_logp[8][16];
    if (gwarp >= NN) return;
    int n = gwarp;
    int cur = (t == 0) ? n : g_walks[n];

    float2 bse = ((const float2*)(g_base + (size_t)n * 64))[lane];
    float2 w2  = ((const float2*)W2)[lane];
    float  b2  = b2p[0];
    const int* nb = dst + (size_t)cur * DEG;
    const int slot_off = (1 + t) * 64;

#pragma unroll
    for (int d = 0; d < DEG; d++) {
        int cand = nb[d];
        float2 c = ((const float2*)(g_SC + (size_t)cand * SC_M + slot_off))[lane];
        float s = fmaxf(bse.x + c.x, 0.f) * w2.x + fmaxf(bse.y + c.y, 0.f) * w2.y;
#pragma unroll
        for (int off = 16; off >= 1; off >>= 1)
            s += __shfl_xor_sync(FULL, s, off);
        if (lane == 0) s_logp[wz][d] = s + b2;
    }
    __syncwarp();

    float lp = (lane < DEG) ? s_logp[wz][lane] : -1e38f;
    float m = lp;
#pragma unroll
    for (int off = 16; off >= 1; off >>= 1)
        m = fmaxf(m, __shfl_xor_sync(FULL, m, off));
    float e = (lane < DEG) ? expf(lp - m) : 0.0f;
    float ssum = e;
#pragma unroll
    for (int off = 16; off >= 1; off >>= 1)
        ssum += __shfl_xor_sync(FULL, ssum, off);
    float norm = m + logf(ssum);
    float p = (lane < DEG)
                  ? expf(lp - norm) + EPS_SEL * noise[((size_t)t * NN + n) * DEG + lane]
                  : -1e38f;
    float bv = p;
    int bi = lane;
#pragma unroll
    for (int off = 16; off >= 1; off >>= 1) {
        float ov = __shfl_xor_sync(FULL, bv, off);
        int oi = __shfl_xor_sync(FULL, bi, off);
        if (ov > bv || (ov == bv && oi < bi)) { bv = ov; bi = oi; }
    }
    int csel = nb[bi];
    float2 c = ((const float2*)(g_SC + (size_t)csel * SC_M + slot_off))[lane];
    bse.x += c.x;
    bse.y += c.y;
    ((float2*)(g_base + (size_t)n * 64))[lane] = bse;
    if (lane == 0) {
        g_walks[n] = csel;
        g_sel[t * NN + n] = csel;
    }
}

// ---------------- GRU elementwise gates ----------------
__global__ void gru_elem(const float* __restrict__ bhh, int s) {
    int i = blockIdx.x * blockDim.x + threadIdx.x;
    if (i >= NN * HID) return;
    int n = i >> 7, c = i & 127;
    int src = (s == 0) ? n : g_sel[(s - 1) * NN + n];
    const float* gi = g_G + (size_t)src * GH_M;
    float gir = gi[c], giz = gi[128 + c], gin = gi[256 + c];
    float ghr, ghz, ghn, hprev;
    if (s == 0) {
        ghr = bhh[c]; ghz = bhh[128 + c]; ghn = bhh[256 + c];
        hprev = 0.0f;
    } else {
        const float* gh = g_GH + (size_t)n * GH_M;
        ghr = gh[c]; ghz = gh[128 + c]; ghn = gh[256 + c];
        hprev = g_h[i];
    }
    float r = 1.0f / (1.0f + expf(-(gir + ghr)));
    float z = 1.0f / (1.0f + expf(-(giz + ghz)));
    float nn2 = tanhf(gin + r * ghn);
    g_h[i] = (1.0f - z) * nn2 + z * hprev;
}

// ---------------- host launch ----------------
extern "C" void kernel_launch(void* const* d_in, const int* in_sizes, int n_in,
                              void* d_out, int out_size) {
    const float* node_attr = (const float*)d_in[0];
    const int*   edge_idx  = (const int*)d_in[1];
    const float* W1   = (const float*)d_in[3];
    const float* b1   = (const float*)d_in[4];
    const float* W2   = (const float*)d_in[5];
    const float* b2   = (const float*)d_in[6];
    const float* Wih  = (const float*)d_in[7];
    const float* Whh  = (const float*)d_in[8];
    const float* bih  = (const float*)d_in[9];
    const float* bhh  = (const float*)d_in[10];
    const float* Wout = (const float*)d_in[11];
    const float* bout = (const float*)d_in[12];
    const float* noise = (const float*)d_in[13];
    float* out = (float*)d_out;
    const int* dst = edge_idx + (size_t)NN * DEG;

    float *pSC, *pG, *pGH, *pH;
    __half *pWihH, *pWihL, *pWhhH, *pWhhL, *pWoutH, *pWoutL;
    cudaGetSymbolAddress((void**)&pSC, g_SC);
    cudaGetSymbolAddress((void**)&pG, g_G);
    cudaGetSymbolAddress((void**)&pGH, g_GH);
    cudaGetSymbolAddress((void**)&pH, g_h);
    cudaGetSymbolAddress((void**)&pWihH, g_Wih_h);
    cudaGetSymbolAddress((void**)&pWihL, g_Wih_l);
    cudaGetSymbolAddress((void**)&pWhhH, g_Whh_h);
    cudaGetSymbolAddress((void**)&pWhhL, g_Whh_l);
    cudaGetSymbolAddress((void**)&pWoutH, g_Wout_h);
    cudaGetSymbolAddress((void**)&pWoutL, g_Wout_l);

    static bool attr_set = false;
    if (!attr_set) {
        cudaFuncSetAttribute(mma_gemm, cudaFuncAttributeMaxDynamicSharedMemorySize, MMA_SMEM);
        attr_set = true;
    }

    // 1. weight prep
    {
        int total = 128 * SC_M + 2 * GH_M * 128 + 128 * 128;
        prep_weights<<<(total + 255) / 256, 256>>>(W1, b1, Wih, Whh, Wout);
    }
    // 2. scoring contribs (fp32, selection-critical) + base init
    {
        dim3 grid(SC_M / 64, (NN + 63) / 64);
        sgemm_score<<<grid, 256>>>(node_attr, pSC, NN);
    }
    // 3. GRU input projection G = v @ Wih^T + bih (tensor cores, fp16x2 split)
    {
        dim3 grid(3, (NN + 127) / 128);
        mma_gemm<<<grid, 256, MMA_SMEM>>>(node_attr, pWihH, pWihL, bih, pG, NN, GH_M);
    }
    // 4. walk-selection steps
    for (int t = 0; t < TT; t++)
        walk_step<<<(NN * 32 + 255) / 256, 256>>>(dst, W2, b2, noise, t);
    // 5. GRU sequence
    gru_elem<<<(NN * HID + 255) / 256, 256>>>(bhh, 0);
    for (int s = 1; s <= TT; s++) {
        dim3 grid(3, (NN + 127) / 128);
        mma_gemm<<<grid, 256, MMA_SMEM>>>(pH, pWhhH, pWhhL, bhh, pGH, NN, GH_M);
        gru_elem<<<(NN * HID + 255) / 256, 256>>>(bhh, s);
    }
    // 6. output projection (tensor cores)
    {
        dim3 grid(1, (NN + 127) / 128);
        mma_gemm<<<grid, 256, MMA_SMEM>>>(pH, pWoutH, pWoutL, bout, out, NN, HID);
    }
}

// round 5
// speedup vs baseline: 1.1336x; 1.0392x over previous
#include <cuda_runtime.h>
#include <cuda_fp16.h>
#include <cstdint>
#include <math.h>

// Problem constants
#define NN      20000
#define DEG     16
#define TT      3
#define HID     128
#define EPS_SEL 0.01f
#define SC_M    256      // 4 slots x 64 scoring cols
#define GH_M    384

// ---------------- device scratch ----------------
__device__ float g_SC   [(size_t)NN * SC_M];
__device__ float g_G    [(size_t)NN * GH_M];
__device__ float g_GH   [(size_t)NN * GH_M];
__device__ float g_base [(size_t)NN * 64];
__device__ float g_h    [(size_t)NN * HID];
__device__ int   g_walks[NN];
__device__ int   g_sel  [TT * NN];
__device__ float g_Bsc_t[SC_M * 128];          // scoring weights [j][k] (B for tf32 GEMM)
__device__ float g_bias_sc[SC_M];
__device__ __half g_Wih_h[GH_M * 128], g_Wih_l[GH_M * 128];   // [n][k]
__device__ __half g_Whh_h[GH_M * 128], g_Whh_l[GH_M * 128];   // [n][k]
__device__ __half g_Wout_h[128 * 128], g_Wout_l[128 * 128];   // [n][k] (transposed)

__device__ __forceinline__ uint32_t smem_u32(const void* p) {
    uint32_t a;
    asm("{ .reg .u64 t; cvta.to.shared.u64 t, %1; cvt.u32.u64 %0, t; }" : "=r"(a) : "l"(p));
    return a;
}
__device__ __forceinline__ uint32_t f2tf32(float x) {
    uint32_t r;
    asm("cvt.rna.tf32.f32 %0, %1;" : "=r"(r) : "f"(x));
    return r;
}

// ---------------- weight prep ----------------
__global__ void prep_weights(const float* __restrict__ W1, const float* __restrict__ b1,
                             const float* __restrict__ Wih, const float* __restrict__ Whh,
                             const float* __restrict__ Wout) {
    int i = blockIdx.x * blockDim.x + threadIdx.x;
    if (i < SC_M * 128) {
        int j = i / 128, k = i % 128;
        int s = j >> 6, m = j & 63;
        g_Bsc_t[i] = W1[(size_t)(s * 128 + k) * 64 + m];
        if (k == 0) g_bias_sc[j] = (j < 64) ? b1[j] : 0.0f;
        return;
    }
    int i2 = i - SC_M * 128;
    float w;
    __half *dh, *dl;
    if (i2 < GH_M * 128) { w = Wih[i2]; dh = g_Wih_h; dl = g_Wih_l; }
    else if (i2 < 2 * GH_M * 128) { i2 -= GH_M * 128; w = Whh[i2]; dh = g_Whh_h; dl = g_Whh_l; }
    else {
        i2 -= 2 * GH_M * 128;
        if (i2 >= 128 * 128) return;
        int n = i2 / 128, k = i2 % 128;
        w = Wout[(size_t)k * 128 + n];
        dh = g_Wout_h; dl = g_Wout_l;
    }
    __half hi = __float2half_rn(w);
    dh[i2] = hi;
    dl[i2] = __float2half_rn(w - __half2float(hi));
}

// ---------------- mma.sync fp16x2-split GEMM (M-tile 64, 2 blocks/SM) ----------------
#define LDS 136   // padded half stride
#define MMA_SMEM (2 * 64 * LDS * 2 + 2 * 128 * LDS * 2)
__global__ __launch_bounds__(256, 2) void mma_gemm(const float* __restrict__ A,
                                                   const __half* __restrict__ Bh,
                                                   const __half* __restrict__ Bl,
                                                   const float* __restrict__ bias,
                                                   float* __restrict__ C, int rows, int ldc) {
    extern __shared__ __align__(16) char smem[];
    const int AH_OFF = 0;
    const int AL_OFF = 64 * LDS * 2;
    const int BH_OFF = 2 * 64 * LDS * 2;
    const int BL_OFF = BH_OFF + 128 * LDS * 2;
    uint32_t sb = smem_u32(smem);

    int tid = threadIdx.x;
    int lane = tid & 31;
    int wid = tid >> 5;
    int wm = wid >> 1, wn = wid & 1;   // 4 x 2 warps; warp tile 16 x 64
    int rowBase = blockIdx.y * 64;

    // ---- load A (fp32 -> hi/lo fp16, padded) : 64 rows x 128 k ----
    for (int c = tid; c < 2048; c += 256) {
        int r = c >> 5, k = (c & 31) * 4;
        int gr = rowBase + r;
        float4 a = make_float4(0.f, 0.f, 0.f, 0.f);
        if (gr < rows) a = *(const float4*)(A + (size_t)gr * 128 + k);
        float av[4] = {a.x, a.y, a.z, a.w};
        __half hv[4], lv[4];
#pragma unroll
        for (int q = 0; q < 4; q++) {
            hv[q] = __float2half_rn(av[q]);
            lv[q] = __float2half_rn(av[q] - __half2float(hv[q]));
        }
        size_t off = ((size_t)r * LDS + k) * 2;
        *(uint2*)(smem + AH_OFF + off) = *(uint2*)hv;
        *(uint2*)(smem + AL_OFF + off) = *(uint2*)lv;
    }
    // ---- load B tiles (pre-split halves) : 128 n x 128 k ----
    {
        const __half* bh = Bh + (size_t)blockIdx.x * 128 * 128;
        const __half* bl = Bl + (size_t)blockIdx.x * 128 * 128;
        for (int c = tid; c < 4096; c += 256) {
            int r = c >> 5, k = (c & 31) * 4;
            size_t off = ((size_t)r * LDS + k) * 2;
            *(uint2*)(smem + BH_OFF + off) = *(const uint2*)(bh + r * 128 + k);
            *(uint2*)(smem + BL_OFF + off) = *(const uint2*)(bl + r * 128 + k);
        }
    }
    __syncthreads();

    float acc[8][4];
#pragma unroll
    for (int ni = 0; ni < 8; ni++)
#pragma unroll
        for (int q = 0; q < 4; q++) acc[ni][q] = 0.0f;

    const int aOffT[3] = {AH_OFF, AH_OFF, AL_OFF};
    const int bOffT[3] = {BH_OFF, BL_OFF, BH_OFF};
    int a_r = lane & 15;
    int a_c = (lane >> 4) * 8;
    int b_r = (lane & 7) + ((lane >> 4) << 3);
    int b_c = ((lane >> 3) & 1) * 8;

#pragma unroll
    for (int term = 0; term < 3; term++) {
        uint32_t abase = sb + aOffT[term];
        uint32_t bbase = sb + bOffT[term];
#pragma unroll
        for (int k0 = 0; k0 < 8; k0++) {
            int kk = k0 * 16;
            uint32_t af[4];
            {
                uint32_t addr = abase + (uint32_t)(((wm * 16 + a_r) * LDS + kk + a_c) * 2);
                asm volatile("ldmatrix.sync.aligned.m8n8.x4.shared.b16 {%0,%1,%2,%3}, [%4];"
                             : "=r"(af[0]), "=r"(af[1]), "=r"(af[2]), "=r"(af[3])
                             : "r"(addr));
            }
            uint32_t bf[8][2];
#pragma unroll
            for (int nj = 0; nj < 4; nj++) {
                uint32_t addr = bbase + (uint32_t)(((wn * 64 + nj * 16 + b_r) * LDS + kk + b_c) * 2);
                uint32_t r0, r1, r2, r3;
                asm volatile("ldmatrix.sync.aligned.m8n8.x4.shared.b16 {%0,%1,%2,%3}, [%4];"
                             : "=r"(r0), "=r"(r1), "=r"(r2), "=r"(r3)
                             : "r"(addr));
                bf[2 * nj][0] = r0; bf[2 * nj][1] = r1;
                bf[2 * nj + 1][0] = r2; bf[2 * nj + 1][1] = r3;
            }
#pragma unroll
            for (int ni = 0; ni < 8; ni++) {
                asm volatile(
                    "mma.sync.aligned.m16n8k16.row.col.f32.f16.f16.f32 "
                    "{%0,%1,%2,%3}, {%4,%5,%6,%7}, {%8,%9}, {%0,%1,%2,%3};"
                    : "+f"(acc[ni][0]), "+f"(acc[ni][1]),
                      "+f"(acc[ni][2]), "+f"(acc[ni][3])
                    : "r"(af[0]), "r"(af[1]), "r"(af[2]), "r"(af[3]),
                      "r"(bf[ni][0]), "r"(bf[ni][1]));
            }
        }
    }

    // ---- epilogue ----
    int rb = rowBase + wm * 16;
    int cb = blockIdx.x * 128 + wn * 64;
#pragma unroll
    for (int ni = 0; ni < 8; ni++) {
        int r0 = rb + (lane >> 2);
        int c0 = cb + ni * 8 + (lane & 3) * 2;
        float bv0 = bias[c0], bv1 = bias[c0 + 1];
        if (r0 < rows) {
            float2 o = make_float2(acc[ni][0] + bv0, acc[ni][1] + bv1);
            *(float2*)(C + (size_t)r0 * ldc + c0) = o;
        }
        if (r0 + 8 < rows) {
            float2 o = make_float2(acc[ni][2] + bv0, acc[ni][3] + bv1);
            *(float2*)(C + (size_t)(r0 + 8) * ldc + c0) = o;
        }
    }
}

// ---------------- 3xTF32 scoring GEMM: C = A[rows,128] @ Bt^T + bias (exact-grade) ----------------
// Block: 64 rows x 128 cols. smem holds plain fp32 tiles; tf32 hi/lo split at frag load.
#define SLDS 132
#define SCORE_SMEM ((64 + 128) * SLDS * 4)
__global__ __launch_bounds__(256, 2) void score_tf32(const float* __restrict__ A, int rows) {
    extern __shared__ float smf[];
    float* As = smf;                 // [64][SLDS]
    float* Bs = smf + 64 * SLDS;     // [128][SLDS]  (B rows = C cols, [n][k])
    int tid = threadIdx.x;
    int lane = tid & 31;
    int wid = tid >> 5;
    int rowBase = blockIdx.y * 64;
    int colBase = blockIdx.x * 128;

    for (int c = tid; c < 2048; c += 256) {
        int r = c >> 5, k = (c & 31) * 4;
        int gr = rowBase + r;
        float4 a = make_float4(0.f, 0.f, 0.f, 0.f);
        if (gr < rows) a = *(const float4*)(A + (size_t)gr * 128 + k);
        *(float4*)(As + r * SLDS + k) = a;
    }
    for (int c = tid; c < 4096; c += 256) {
        int r = c >> 5, k = (c & 31) * 4;
        float4 b = *(const float4*)(g_Bsc_t + (size_t)(colBase + r) * 128 + k);
        *(float4*)(Bs + r * SLDS + k) = b;
    }
    __syncthreads();

    int wm = wid >> 1, wn = wid & 1;       // warp tile 16 x 64
    int m0 = wm * 16, n0 = wn * 64;
    int gid = lane >> 2, tig = lane & 3;

    float acc[8][4];
#pragma unroll
    for (int ni = 0; ni < 8; ni++)
#pragma unroll
        for (int q = 0; q < 4; q++) acc[ni][q] = 0.0f;

#pragma unroll
    for (int k0 = 0; k0 < 16; k0++) {
        int kk = k0 * 8;
        float a0 = As[(m0 + gid) * SLDS + kk + tig];
        float a1 = As[(m0 + gid + 8) * SLDS + kk + tig];
        float a2 = As[(m0 + gid) * SLDS + kk + tig + 4];
        float a3 = As[(m0 + gid + 8) * SLDS + kk + tig + 4];
        uint32_t ah[4], al[4];
        float av[4] = {a0, a1, a2, a3};
#pragma unroll
        for (int q = 0; q < 4; q++) {
            ah[q] = f2tf32(av[q]);
            al[q] = f2tf32(av[q] - __uint_as_float(ah[q]));
        }
#pragma unroll
        for (int nf = 0; nf < 8; nf++) {
            float b0 = Bs[(n0 + nf * 8 + gid) * SLDS + kk + tig];
            float b1 = Bs[(n0 + nf * 8 + gid) * SLDS + kk + tig + 4];
            uint32_t bh0 = f2tf32(b0), bh1 = f2tf32(b1);
            uint32_t bl0 = f2tf32(b0 - __uint_as_float(bh0));
            uint32_t bl1 = f2tf32(b1 - __uint_as_float(bh1));
            // hh
            asm volatile(
                "mma.sync.aligned.m16n8k8.row.col.f32.tf32.tf32.f32 "
                "{%0,%1,%2,%3}, {%4,%5,%6,%7}, {%8,%9}, {%0,%1,%2,%3};"
                : "+f"(acc[nf][0]), "+f"(acc[nf][1]), "+f"(acc[nf][2]), "+f"(acc[nf][3])
                : "r"(ah[0]), "r"(ah[1]), "r"(ah[2]), "r"(ah[3]), "r"(bh0), "r"(bh1));
            // hl
            asm volatile(
                "mma.sync.aligned.m16n8k8.row.col.f32.tf32.tf32.f32 "
                "{%0,%1,%2,%3}, {%4,%5,%6,%7}, {%8,%9}, {%0,%1,%2,%3};"
                : "+f"(acc[nf][0]), "+f"(acc[nf][1]), "+f"(acc[nf][2]), "+f"(acc[nf][3])
                : "r"(ah[0]), "r"(ah[1]), "r"(ah[2]), "r"(ah[3]), "r"(bl0), "r"(bl1));
            // lh
            asm volatile(
                "mma.sync.aligned.m16n8k8.row.col.f32.tf32.tf32.f32 "
                "{%0,%1,%2,%3}, {%4,%5,%6,%7}, {%8,%9}, {%0,%1,%2,%3};"
                : "+f"(acc[nf][0]), "+f"(acc[nf][1]), "+f"(acc[nf][2]), "+f"(acc[nf][3])
                : "r"(al[0]), "r"(al[1]), "r"(al[2]), "r"(al[3]), "r"(bh0), "r"(bh1));
        }
    }

    // epilogue: write g_SC and init g_base from slot 0
    int rb = rowBase + m0;
#pragma unroll
    for (int nf = 0; nf < 8; nf++) {
        int c0 = colBase + n0 + nf * 8 + tig * 2;
        float bv0 = g_bias_sc[c0], bv1 = g_bias_sc[c0 + 1];
#pragma unroll
        for (int half = 0; half < 2; half++) {
            int r0 = rb + gid + half * 8;
            if (r0 >= rows) continue;
            float v0 = acc[nf][2 * half + 0] + bv0;
            float v1 = acc[nf][2 * half + 1] + bv1;
            *(float2*)(g_SC + (size_t)r0 * SC_M + c0) = make_float2(v0, v1);
            if (c0 < 64)
                *(float2*)(g_base + (size_t)r0 * 64 + c0) = make_float2(v0, v1);
        }
    }
}

// ---------------- walk step: one warp per node ----------------
__global__ void walk_step(const int* __restrict__ dst, const float* __restrict__ W2,
                          const float* __restrict__ b2p, const float* __restrict__ noise,
                          int t) {
    const unsigned FULL = 0xFFFFFFFFu;
    int gwarp = (blockIdx.x * blockDim.x + threadIdx.x) >> 5;
    int lane = threadIdx.x & 31;
    int wz = threadIdx.x >> 5;
    __shared__ float s_logp[8][16];
    if (gwarp >= NN) return;
    int n = gwarp;
    int cur = (t == 0) ? n : g_walks[n];

    float2 bse = ((const float2*)(g_base + (size_t)n * 64))[lane];
    float2 w2  = ((const float2*)W2)[lane];
    float  b2  = b2p[0];
    const int* nb = dst + (size_t)cur * DEG;
    const int slot_off = (1 + t) * 64;

#pragma unroll
    for (int d = 0; d < DEG; d++) {
        int cand = nb[d];
        float2 c = ((const float2*)(g_SC + (size_t)cand * SC_M + slot_off))[lane];
        float s = fmaxf(bse.x + c.x, 0.f) * w2.x + fmaxf(bse.y + c.y, 0.f) * w2.y;
#pragma unroll
        for (int off = 16; off >= 1; off >>= 1)
            s += __shfl_xor_sync(FULL, s, off);
        if (lane == 0) s_logp[wz][d] = s + b2;
    }
    __syncwarp();

    float lp = (lane < DEG) ? s_logp[wz][lane] : -1e38f;
    float m = lp;
#pragma unroll
    for (int off = 16; off >= 1; off >>= 1)
        m = fmaxf(m, __shfl_xor_sync(FULL, m, off));
    float e = (lane < DEG) ? expf(lp - m) : 0.0f;
    float ssum = e;
#pragma unroll
    for (int off = 16; off >= 1; off >>= 1)
        ssum += __shfl_xor_sync(FULL, ssum, off);
    float norm = m + logf(ssum);
    float p = (lane < DEG)
                  ? expf(lp - norm) + EPS_SEL * noise[((size_t)t * NN + n) * DEG + lane]
                  : -1e38f;
    float bv = p;
    int bi = lane;
#pragma unroll
    for (int off = 16; off >= 1; off >>= 1) {
        float ov = __shfl_xor_sync(FULL, bv, off);
        int oi = __shfl_xor_sync(FULL, bi, off);
        if (ov > bv || (ov == bv && oi < bi)) { bv = ov; bi = oi; }
    }
    int csel = nb[bi];
    float2 c = ((const float2*)(g_SC + (size_t)csel * SC_M + slot_off))[lane];
    bse.x += c.x;
    bse.y += c.y;
    ((float2*)(g_base + (size_t)n * 64))[lane] = bse;
    if (lane == 0) {
        g_walks[n] = csel;
        g_sel[t * NN + n] = csel;
    }
}

// ---------------- GRU elementwise gates ----------------
__global__ void gru_elem(const float* __restrict__ bhh, int s) {
    int i = blockIdx.x * blockDim.x + threadIdx.x;
    if (i >= NN * HID) return;
    int n = i >> 7, c = i & 127;
    int src = (s == 0) ? n : g_sel[(s - 1) * NN + n];
    const float* gi = g_G + (size_t)src * GH_M;
    float gir = gi[c], giz = gi[128 + c], gin = gi[256 + c];
    float ghr, ghz, ghn, hprev;
    if (s == 0) {
        ghr = bhh[c]; ghz = bhh[128 + c]; ghn = bhh[256 + c];
        hprev = 0.0f;
    } else {
        const float* gh = g_GH + (size_t)n * GH_M;
        ghr = gh[c]; ghz = gh[128 + c]; ghn = gh[256 + c];
        hprev = g_h[i];
    }
    float r = 1.0f / (1.0f + expf(-(gir + ghr)));
    float z = 1.0f / (1.0f + expf(-(giz + ghz)));
    float nn2 = tanhf(gin + r * ghn);
    g_h[i] = (1.0f - z) * nn2 + z * hprev;
}

// ---------------- host launch ----------------
extern "C" void kernel_launch(void* const* d_in, const int* in_sizes, int n_in,
                              void* d_out, int out_size) {
    const float* node_attr = (const float*)d_in[0];
    const int*   edge_idx  = (const int*)d_in[1];
    const float* W1   = (const float*)d_in[3];
    const float* b1   = (const float*)d_in[4];
    const float* W2   = (const float*)d_in[5];
    const float* b2   = (const float*)d_in[6];
    const float* Wih  = (const float*)d_in[7];
    const float* Whh  = (const float*)d_in[8];
    const float* bih  = (const float*)d_in[9];
    const float* bhh  = (const float*)d_in[10];
    const float* Wout = (const float*)d_in[11];
    const float* bout = (const float*)d_in[12];
    const float* noise = (const float*)d_in[13];
    float* out = (float*)d_out;
    const int* dst = edge_idx + (size_t)NN * DEG;

    float *pG, *pGH, *pH;
    __half *pWihH, *pWihL, *pWhhH, *pWhhL, *pWoutH, *pWoutL;
    cudaGetSymbolAddress((void**)&pG, g_G);
    cudaGetSymbolAddress((void**)&pGH, g_GH);
    cudaGetSymbolAddress((void**)&pH, g_h);
    cudaGetSymbolAddress((void**)&pWihH, g_Wih_h);
    cudaGetSymbolAddress((void**)&pWihL, g_Wih_l);
    cudaGetSymbolAddress((void**)&pWhhH, g_Whh_h);
    cudaGetSymbolAddress((void**)&pWhhL, g_Whh_l);
    cudaGetSymbolAddress((void**)&pWoutH, g_Wout_h);
    cudaGetSymbolAddress((void**)&pWoutL, g_Wout_l);

    static bool attr_set = false;
    if (!attr_set) {
        cudaFuncSetAttribute(mma_gemm, cudaFuncAttributeMaxDynamicSharedMemorySize, MMA_SMEM);
        cudaFuncSetAttribute(score_tf32, cudaFuncAttributeMaxDynamicSharedMemorySize, SCORE_SMEM);
        attr_set = true;
    }

    // 1. weight prep
    {
        int total = SC_M * 128 + 2 * GH_M * 128 + 128 * 128;
        prep_weights<<<(total + 255) / 256, 256>>>(W1, b1, Wih, Whh, Wout);
    }
    // 2. scoring contribs (3xTF32, fp32-grade) + base init
    {
        dim3 grid(2, (NN + 63) / 64);
        score_tf32<<<grid, 256, SCORE_SMEM>>>(node_attr, NN);
    }
    // 3. GRU input projection G = v @ Wih^T + bih
    {
        dim3 grid(3, (NN + 63) / 64);
        mma_gemm<<<grid, 256, MMA_SMEM>>>(node_attr, pWihH, pWihL, bih, pG, NN, GH_M);
    }
    // 4. walk-selection steps
    for (int t = 0; t < TT; t++)
        walk_step<<<(NN * 32 + 255) / 256, 256>>>(dst, W2, b2, noise, t);
    // 5. GRU sequence
    gru_elem<<<(NN * HID + 255) / 256, 256>>>(bhh, 0);
    for (int s = 1; s <= TT; s++) {
        dim3 grid(3, (NN + 63) / 64);
        mma_gemm<<<grid, 256, MMA_SMEM>>>(pH, pWhhH, pWhhL, bhh, pGH, NN, GH_M);
        gru_elem<<<(NN * HID + 255) / 256, 256>>>(bhh, s);
    }
    // 6. output projection
    {
        dim3 grid(1, (NN + 63) / 64);
        mma_gemm<<<grid, 256, MMA_SMEM>>>(pH, pWoutH, pWoutL, bout, out, NN, HID);
    }
}